// round 5
// baseline (speedup 1.0000x reference)
#include <cuda_runtime.h>
#include <math.h>

#define BSZ  1024
#define SLEN 512
#define TT   64
#define KRN  5    // renormalize every KRN unmasked steps (exact pow-2 scaling, applied next step)

__device__ double g_res[BSZ];
__device__ int    g_cnt[BSZ];
__device__ int    g_ticket;    // zero-init; last block resets to 0 (replay-safe)

static __device__ __forceinline__ unsigned long long pk2(float x, float y) {
    unsigned long long r;
    asm("mov.b64 %0, {%1, %2};" : "=l"(r) : "f"(x), "f"(y));
    return r;
}
static __device__ __forceinline__ float2 upk2(unsigned long long v) {
    float2 r;
    asm("mov.b64 {%0, %1}, %2;" : "=f"(r.x), "=f"(r.y) : "l"(v));
    return r;
}
// Packed fp32x2 FMA (Blackwell): both halves independent MACs -> SASS FFMA2
static __device__ __forceinline__ unsigned long long ffma2(unsigned long long a,
                                                           unsigned long long b,
                                                           unsigned long long c) {
    unsigned long long d;
    asm("fma.rn.f32x2 %0, %1, %2, %3;" : "=l"(d) : "l"(a), "l"(b), "l"(c));
    return d;
}
static __device__ __forceinline__ unsigned long long fadd2(unsigned long long a,
                                                           unsigned long long b) {
    unsigned long long d;
    asm("add.rn.f32x2 %0, %1, %2;" : "=l"(d) : "l"(a), "l"(b));
    return d;
}

// One block (64 threads = 2 warps) per chain. Lane owns ONE column c = threadIdx.x.
__global__ __launch_bounds__(64, 8)
void crf_forward(const float* __restrict__ e, const int* __restrict__ tags,
                 const unsigned char* __restrict__ mask,
                 const float* __restrict__ st, const float* __restrict__ et,
                 const float* __restrict__ tmat, float* __restrict__ out)
{
    __shared__ __align__(16) float pbuf[2][TT];   // p vector, double buffered
    __shared__ float sm_mx[2];                    // cross-warp max exchange
    __shared__ float sm_red[2];                   // cross-warp scalar sums
    __shared__ int   sm_cnt[2];
    __shared__ int   s_t;

    const int tid   = threadIdx.x;      // 0..63
    const int lane  = tid & 31;
    const int half  = tid >> 5;         // warp index within chain
    const int chain = blockIdx.x;
    const int c     = tid;              // owned column

    const float*         eb = e    + (size_t)chain * (SLEN * TT);
    const int*           tb = tags + chain * SLEN;
    const unsigned char* mb = mask + chain * SLEN;

    // ---- exp(transition) in registers: Ep[m] = (E[2m][c], E[2m+1][c]) ----
    unsigned long long Ep[32];
#pragma unroll
    for (int m = 0; m < 32; ++m) {
        float a = __expf(__ldg(&tmat[(2 * m)     * TT + c]));
        float b = __expf(__ldg(&tmat[(2 * m + 1) * TT + c]));
        Ep[m] = pk2(a, b);
    }

    // ---- tag-path score + mask count (both warps, s strided by 64) ----
    float scp = 0.f;
    int cntp = 0;
#pragma unroll 1
    for (int s = tid; s < SLEN; s += 64) {
        int m = mb[s];
        cntp += m;
        if (s > 0 && m) {
            int tp = tb[s - 1], tn = tb[s];
            scp += __ldg(&tmat[tp * TT + tn]) + eb[s * TT + tn];
        }
    }
#pragma unroll
    for (int off = 16; off; off >>= 1) {
        scp  += __shfl_xor_sync(0xffffffffu, scp, off);
        cntp += __shfl_xor_sync(0xffffffffu, cntp, off);
    }
    if (lane == 0) { sm_red[half] = scp; sm_cnt[half] = cntp; }
    __syncthreads();
    const int   cnt_tot = sm_cnt[0] + sm_cnt[1];
    const float scp_tot = sm_red[0] + sm_red[1];
    const int   t0      = tb[0];
    const int   tlast   = tb[cnt_tot - 1];
    const float score   = scp_tot + st[t0] + eb[t0] + et[tlast];
    __syncthreads();

    // ---- forward-vector init (step 0): p[c] = exp(st[c]+e0[c] - base) ----
    float n = st[c] + eb[c];
    float base = n;
#pragma unroll
    for (int off = 16; off; off >>= 1)
        base = fmaxf(base, __shfl_xor_sync(0xffffffffu, base, off));
    if (lane == 0) sm_mx[half] = base;
    __syncthreads();
    base = fmaxf(sm_mx[0], sm_mx[1]);
    float plast = __expf(n - base);
    pbuf[0][c] = plast;
    int cur = 0;
    int Eacc = 0;            // accumulated power-of-two scale (exact)
    int rc = 0;              // unmasked steps since last renorm
    int rpend = 0;           // renorm measured last step, apply this step
    __syncthreads();

    // one step: q[c] = (sum_i p[i]*E[i][c]) * exp(e[c]) (* 2^-ke if pending)
    auto do_step = [&](float ec, int mk) {
        if (!mk) return;
        float F = __expf(ec);
        if (rpend) {                                 // apply deferred exact pow-2 renorm
            float mx = fmaxf(sm_mx[0], sm_mx[1]);
            int ke = (__float_as_int(mx) >> 23) - 127;
            F *= __int_as_float((127 - ke) << 23);   // exact 2^-ke
            Eacc += ke;
            rpend = 0;
        }
        const ulonglong2* rp = reinterpret_cast<const ulonglong2*>(pbuf[cur]);
        unsigned long long a0 = 0ull, a1 = 0ull, a2 = 0ull, a3 = 0ull;
#pragma unroll
        for (int k = 0; k < 8; ++k) {
            ulonglong2 v0 = rp[2 * k];       // (p[4k],p[4k+1]) packed as 2 f32x2
            ulonglong2 v1 = rp[2 * k + 1];
            a0 = ffma2(v0.x, Ep[4 * k],     a0);
            a1 = ffma2(v0.y, Ep[4 * k + 1], a1);
            a2 = ffma2(v1.x, Ep[4 * k + 2], a2);
            a3 = ffma2(v1.y, Ep[4 * k + 3], a3);
        }
        float2 sres = upk2(fadd2(fadd2(a0, a1), fadd2(a2, a3)));
        float q = (sres.x + sres.y) * F;
        if (++rc >= KRN) {                 // measure warp max; applied next step
            rc = 0;
            float loc = q;
#pragma unroll
            for (int off = 16; off; off >>= 1)
                loc = fmaxf(loc, __shfl_xor_sync(0xffffffffu, loc, off));
            if (lane == 0) sm_mx[half] = loc;
            rpend = 1;
        }
        cur ^= 1;
        pbuf[cur][c] = q;
        plast = q;
        __syncthreads();
    };

    // ---- main loop, software prefetch distance 2, unrolled x2 ----
    float eA = eb[1 * TT + c]; int mA = mb[1];
    float eB = eb[2 * TT + c]; int mB = mb[2];
#pragma unroll 1
    for (int s = 1; s < SLEN; s += 2) {
        float ec = eA; int mk = mA;
        if (s + 2 < SLEN) { eA = eb[(s + 2) * TT + c]; mA = mb[s + 2]; }
        do_step(ec, mk);
        if (s + 1 < SLEN) {
            float ec2 = eB; int mk2 = mB;
            if (s + 3 < SLEN) { eB = eb[(s + 3) * TT + c]; mB = mb[s + 3]; }
            do_step(ec2, mk2);
        }
    }
    // NOTE: a still-pending renorm cancels exactly: logZ = base + Eacc*ln2 + log(sum p*exp(et))

    // ---- logZ, per-chain result ----
    float z = plast * __expf(et[c]);
#pragma unroll
    for (int off = 16; off; off >>= 1)
        z += __shfl_xor_sync(0xffffffffu, z, off);
    if (lane == 0) sm_red[half] = z;
    __syncthreads();
    if (tid == 0) {
        double logZ = (double)base + (double)Eacc * 0.6931471805599453094
                    + log((double)(sm_red[0] + sm_red[1]));
        g_res[chain] = (double)score - logZ;
        g_cnt[chain] = cnt_tot;
    }

    // ---- last-block fused finalization (deterministic order) ----
    __syncthreads();
    if (tid == 0) {
        __threadfence();
        s_t = atomicAdd(&g_ticket, 1);
    }
    __syncthreads();
    if (s_t == (int)gridDim.x - 1) {
        double acc = 0.0;
        int    cnt = 0;
#pragma unroll
        for (int i = 0; i < BSZ / 64; ++i) {   // 16 chains per thread
            int idx = tid + i * 64;
            acc += g_res[idx];
            cnt += g_cnt[idx];
        }
#pragma unroll
        for (int off = 16; off; off >>= 1) {
            acc += __shfl_xor_sync(0xffffffffu, acc, off);
            cnt += __shfl_xor_sync(0xffffffffu, cnt, off);
        }
        if (lane == 0) { sm_red[half] = (float)0; sm_cnt[half] = cnt; }
        __shared__ double sacc2[2];
        if (lane == 0) sacc2[half] = acc;
        __syncthreads();
        if (tid == 0) {
            double ta = sacc2[0] + sacc2[1];
            int    tc = sm_cnt[0] + sm_cnt[1];
            out[0] = (float)(ta / (double)tc);
            g_ticket = 0;                      // reset for next graph replay
        }
    }
}

extern "C" void kernel_launch(void* const* d_in, const int* in_sizes, int n_in,
                              void* d_out, int out_size)
{
    const float*         e    = (const float*)d_in[0];
    const int*           tags = (const int*)d_in[1];
    const unsigned char* mask = (const unsigned char*)d_in[2];
    const float*         st   = (const float*)d_in[3];
    const float*         et   = (const float*)d_in[4];
    const float*         t    = (const float*)d_in[5];

    crf_forward<<<BSZ, 64>>>(e, tags, mask, st, et, t, (float*)d_out);
}

// round 6
// speedup vs baseline: 1.9134x; 1.9134x over previous
#include <cuda_runtime.h>
#include <math.h>

#define BSZ  1024
#define SLEN 512
#define TT   64
#define NW   2    // warps (=independent chains) per block
#define KRN  6    // renormalize every KRN unmasked steps (exact pow-2, numerics-invariant)

__device__ double g_res[BSZ];
__device__ int    g_cnt[BSZ];
__device__ int    g_ticket;    // zero-init; last block resets to 0 (replay-safe)

static __device__ __forceinline__ unsigned long long pk2(float x, float y) {
    unsigned long long r;
    asm("mov.b64 %0, {%1, %2};" : "=l"(r) : "f"(x), "f"(y));
    return r;
}
static __device__ __forceinline__ float2 upk2(unsigned long long v) {
    float2 r;
    asm("mov.b64 {%0, %1}, %2;" : "=f"(r.x), "=f"(r.y) : "l"(v));
    return r;
}
static __device__ __forceinline__ unsigned long long ffma2(unsigned long long a,
                                                           unsigned long long b,
                                                           unsigned long long c) {
    unsigned long long d;
    asm("fma.rn.f32x2 %0, %1, %2, %3;" : "=l"(d) : "l"(a), "l"(b), "l"(c));
    return d;
}
static __device__ __forceinline__ unsigned long long fadd2(unsigned long long a,
                                                           unsigned long long b) {
    unsigned long long d;
    asm("add.rn.f32x2 %0, %1, %2;" : "=l"(d) : "l"(a), "l"(b));
    return d;
}
static __device__ __forceinline__ unsigned long long fmul2(unsigned long long a,
                                                           unsigned long long b) {
    unsigned long long d;
    asm("mul.rn.f32x2 %0, %1, %2;" : "=l"(d) : "l"(a), "l"(b));
    return d;
}

__global__ __launch_bounds__(NW * 32, 4)
void crf_forward(const float* __restrict__ e, const int* __restrict__ tags,
                 const unsigned char* __restrict__ mask,
                 const float* __restrict__ st, const float* __restrict__ et,
                 const float* __restrict__ tmat, float* __restrict__ out)
{
    // duplicated-p arrays, double buffered per warp: pd[w][buf][i] = (p_i, p_i)
    __shared__ __align__(16) unsigned long long pd[NW][2][TT];
    __shared__ int s_t;

    const int w     = threadIdx.x >> 5;
    const int lane  = threadIdx.x & 31;
    const int chain = blockIdx.x * NW + w;
    const int c0 = 2 * lane, c1 = c0 + 1;   // this lane's two (adjacent) columns

    const float*         eb = e    + (size_t)chain * (SLEN * TT);
    const int*           tb = tags + chain * SLEN;
    const unsigned char* mb = mask + chain * SLEN;

    // ---- exp(transition) in registers: Ep[i] = (E[i][c0], E[i][c1]) ----
    unsigned long long Ep[TT];
#pragma unroll
    for (int i = 0; i < TT; ++i) {
        const float2 tv = *reinterpret_cast<const float2*>(&tmat[i * TT + c0]);
        Ep[i] = pk2(__expf(tv.x), __expf(tv.y));
    }

    // ---- tag-path score + mask count (gathers, lanes stride over s) ----
    float scp = 0.f;
    int cntp = 0;
#pragma unroll 4
    for (int s = lane; s < SLEN; s += 32) {
        int m = mb[s];
        cntp += m;
        if (s > 0 && m) {
            int tp = tb[s - 1], tn = tb[s];
            scp += __ldg(&tmat[tp * TT + tn]) + eb[s * TT + tn];
        }
    }
#pragma unroll
    for (int off = 16; off; off >>= 1) {
        scp  += __shfl_xor_sync(0xffffffffu, scp, off);
        cntp += __shfl_xor_sync(0xffffffffu, cntp, off);
    }
    int   t0    = tb[0];
    int   tlast = tb[cntp - 1];
    float score = scp + st[t0] + eb[t0] + et[tlast];

    // ---- forward-vector init (step 0) ----
    float2 ev0 = *reinterpret_cast<const float2*>(eb + c0);
    float n0 = st[c0] + ev0.x;
    float n1 = st[c1] + ev0.y;
    float base = fmaxf(n0, n1);
#pragma unroll
    for (int off = 16; off; off >>= 1)
        base = fmaxf(base, __shfl_xor_sync(0xffffffffu, base, off));
    float p0 = __expf(n0 - base);
    float p1 = __expf(n1 - base);
    *reinterpret_cast<ulonglong2*>(&pd[w][0][c0]) =
        make_ulonglong2(pk2(p0, p0), pk2(p1, p1));
    int cur  = 0;
    int Eacc = 0;   // accumulated power-of-two scale (exact)
    int rc   = 0;   // unmasked steps since last renorm
    __syncwarp();

    // one step: q_c = (sum_i p_i E[i][c]) * exp(e_c); exact pow-2 renorm every KRN
    auto do_step = [&](float2 ec, int mk) {
        if (!mk) return;
        unsigned long long F = pk2(__expf(ec.x), __expf(ec.y));
        const ulonglong2* rp = reinterpret_cast<const ulonglong2*>(pd[w][cur]);
        unsigned long long a0 = 0ull, a1 = 0ull, a2 = 0ull, a3 = 0ull;
        unsigned long long a4 = 0ull, a5 = 0ull, a6 = 0ull, a7 = 0ull;
#pragma unroll
        for (int k = 0; k < 8; ++k) {
            ulonglong2 v0 = rp[4 * k];
            ulonglong2 v1 = rp[4 * k + 1];
            ulonglong2 v2 = rp[4 * k + 2];
            ulonglong2 v3 = rp[4 * k + 3];
            a0 = ffma2(v0.x, Ep[8 * k],     a0);
            a1 = ffma2(v0.y, Ep[8 * k + 1], a1);
            a2 = ffma2(v1.x, Ep[8 * k + 2], a2);
            a3 = ffma2(v1.y, Ep[8 * k + 3], a3);
            a4 = ffma2(v2.x, Ep[8 * k + 4], a4);
            a5 = ffma2(v2.y, Ep[8 * k + 5], a5);
            a6 = ffma2(v3.x, Ep[8 * k + 6], a6);
            a7 = ffma2(v3.y, Ep[8 * k + 7], a7);
        }
        unsigned long long qp = fmul2(
            fadd2(fadd2(fadd2(a0, a1), fadd2(a2, a3)),
                  fadd2(fadd2(a4, a5), fadd2(a6, a7))), F);
        float2 q = upk2(qp);
        float q0 = q.x, q1 = q.y;
        if (++rc >= KRN) {      // amortized exact pow-2 renormalization
            rc = 0;
            float loc = fmaxf(q0, q1);
#pragma unroll
            for (int off = 16; off; off >>= 1)
                loc = fmaxf(loc, __shfl_xor_sync(0xffffffffu, loc, off));
            int ke = (__float_as_int(loc) >> 23) - 127;     // floor(log2(max q))
            Eacc += ke;
            float rinv = __int_as_float((127 - ke) << 23);  // exact 2^-ke
            q0 *= rinv;
            q1 *= rinv;
        }
        p0 = q0;
        p1 = q1;
        cur ^= 1;
        *reinterpret_cast<ulonglong2*>(&pd[w][cur][c0]) =
            make_ulonglong2(pk2(q0, q0), pk2(q1, q1));
        __syncwarp();
    };

    // ---- main loop: prefetch distance 4, unrolled x4 ----
    float2 eA, eB, eC, eD;
    int mA = 0, mB = 0, mC = 0, mD = 0;
    eA = *reinterpret_cast<const float2*>(eb + 1 * TT + c0); mA = mb[1];
    eB = *reinterpret_cast<const float2*>(eb + 2 * TT + c0); mB = mb[2];
    eC = *reinterpret_cast<const float2*>(eb + 3 * TT + c0); mC = mb[3];
    eD = *reinterpret_cast<const float2*>(eb + 4 * TT + c0); mD = mb[4];
#pragma unroll 1
    for (int s = 1; s < SLEN; s += 4) {
        float2 c_eA = eA, c_eB = eB, c_eC = eC, c_eD = eD;
        int    c_mA = mA, c_mB = mB, c_mC = mC, c_mD = mD;
        if (s + 4 < SLEN) { eA = *reinterpret_cast<const float2*>(eb + (s + 4) * TT + c0); mA = mb[s + 4]; }
        if (s + 5 < SLEN) { eB = *reinterpret_cast<const float2*>(eb + (s + 5) * TT + c0); mB = mb[s + 5]; }
        if (s + 6 < SLEN) { eC = *reinterpret_cast<const float2*>(eb + (s + 6) * TT + c0); mC = mb[s + 6]; }
        if (s + 7 < SLEN) { eD = *reinterpret_cast<const float2*>(eb + (s + 7) * TT + c0); mD = mb[s + 7]; }
        do_step(c_eA, c_mA);
        if (s + 1 < SLEN) do_step(c_eB, c_mB);
        if (s + 2 < SLEN) do_step(c_eC, c_mC);
        if (s + 3 < SLEN) do_step(c_eD, c_mD);
    }

    // ---- logZ, per-chain result ----
    float z = p0 * __expf(et[c0]) + p1 * __expf(et[c1]);
#pragma unroll
    for (int off = 16; off; off >>= 1)
        z += __shfl_xor_sync(0xffffffffu, z, off);
    if (lane == 0) {
        double logZ = (double)base + (double)Eacc * 0.6931471805599453094
                    + log((double)z);
        g_res[chain] = (double)score - logZ;
        g_cnt[chain] = cntp;
    }

    // ---- last-block fused finalization (deterministic order) ----
    __syncthreads();
    if (threadIdx.x == 0) {
        __threadfence();
        s_t = atomicAdd(&g_ticket, 1);
    }
    __syncthreads();
    if (s_t == (int)gridDim.x - 1) {
        const int tid = threadIdx.x;       // 64 threads
        double acc = 0.0;
        int    cnt = 0;
#pragma unroll
        for (int i = 0; i < BSZ / (NW * 32); ++i) {   // 16 chains per thread
            int idx = tid + i * (NW * 32);
            acc += g_res[idx];
            cnt += g_cnt[idx];
        }
#pragma unroll
        for (int off = 16; off; off >>= 1) {
            acc += __shfl_xor_sync(0xffffffffu, acc, off);
            cnt += __shfl_xor_sync(0xffffffffu, cnt, off);
        }
        __shared__ double sacc[NW];
        __shared__ int    scnt[NW];
        if (lane == 0) { sacc[w] = acc; scnt[w] = cnt; }
        __syncthreads();
        if (tid == 0) {
            double ta = 0.0; int tc = 0;
#pragma unroll
            for (int i = 0; i < NW; ++i) { ta += sacc[i]; tc += scnt[i]; }
            out[0] = (float)(ta / (double)tc);
            g_ticket = 0;                      // reset for next graph replay
        }
    }
}

extern "C" void kernel_launch(void* const* d_in, const int* in_sizes, int n_in,
                              void* d_out, int out_size)
{
    const float*         e    = (const float*)d_in[0];
    const int*           tags = (const int*)d_in[1];
    const unsigned char* mask = (const unsigned char*)d_in[2];
    const float*         st   = (const float*)d_in[3];
    const float*         et   = (const float*)d_in[4];
    const float*         t    = (const float*)d_in[5];

    crf_forward<<<BSZ / NW, NW * 32>>>(e, tags, mask, st, et, t, (float*)d_out);
}